// round 3
// baseline (speedup 1.0000x reference)
#include <cuda_runtime.h>
#include <math.h>

#define NB 8
#define NT 64
#define NN 512
#define NH 256
#define NOUT 512
#define NFLEN 24
#define NBLK 128
#define NSTEP 88
#define SHSTRIDE 272   /* 256 + 16 pad: b*272 mod 32 = 16 -> conflict-free LDS.128 */

// ---------------- device scratch (no allocations allowed) ----------------
__device__ float d_xg[NB * NT * NN];          // GAT output  [B,T,N]
__device__ float d_G[NB * NT * 4 * NH];       // enc input preacts
__device__ float d_Weff[4 * NH * NH];         // dec_Wih @ fc_W
__device__ float d_hbuf[NSTEP * 2048];        // per-step h, sentinel 0xFF

// ============================= GAT kernel =================================
// Per (b,t): e_ij = LR(a0 f_i + a1 f_j), adj==1. Sort v_j = a1 f_j ascending,
// build exclusive prefix scans of (e1, e2, f e1, f e2); per-i the predicated
// softmax sums become a binary search + two scan lookups.
__global__ __launch_bounds__(512) void gat_kernel(const float* __restrict__ x,
                                                  const float* __restrict__ gatW,
                                                  const float* __restrict__ gata) {
    __shared__ float  sk[512];      // sorted keys v
    __shared__ float  sf[512];      // payload f (sorted alongside)
    __shared__ float4 ssum[512];    // exclusive prefix of (e1,e2,fe1,fe2)
    __shared__ float  sred[16];
    __shared__ float4 swt[16];      // warp totals
    __shared__ float4 swo[16];      // warp exclusive offsets

    int bt = blockIdx.x, tid = threadIdx.x;
    int lane = tid & 31, wid = tid >> 5;
    float W = gatW[0], a0 = gata[0], a1 = gata[1];
    float fi = x[bt * NN + tid] * W;
    float v = a1 * fi;

    // block max of v
    float m = v;
    #pragma unroll
    for (int s = 16; s; s >>= 1) m = fmaxf(m, __shfl_xor_sync(0xffffffffu, m, s));
    if (lane == 0) sred[wid] = m;
    __syncthreads();
    if (tid < 32) {
        float t2 = (tid < 16) ? sred[tid] : -3.4e38f;
        #pragma unroll
        for (int s = 8; s; s >>= 1) t2 = fmaxf(t2, __shfl_xor_sync(0xffffffffu, t2, s));
        if (tid == 0) sred[0] = t2;
    }
    sk[tid] = v;
    sf[tid] = fi;
    __syncthreads();
    float vmax = sred[0];

    // bitonic sort ascending by key, payload carried
    for (int k = 2; k <= 512; k <<= 1) {
        for (int j = k >> 1; j > 0; j >>= 1) {
            int ixj = tid ^ j;
            if (ixj > tid) {
                float ka = sk[tid], kb = sk[ixj];
                bool up = ((tid & k) == 0);
                if ((ka > kb) == up) {
                    sk[tid] = kb; sk[ixj] = ka;
                    float t = sf[tid]; sf[tid] = sf[ixj]; sf[ixj] = t;
                }
            }
            __syncthreads();
        }
    }

    // payload in sorted order
    float vs = sk[tid], fs = sf[tid];
    float p1 = __expf(vs - vmax);
    float p2 = __expf(0.2f * (vs - vmax));
    float4 pl = make_float4(p1, p2, fs * p1, fs * p2);

    // inclusive warp scan
    float4 s4 = pl;
    #pragma unroll
    for (int off = 1; off < 32; off <<= 1) {
        float nx = __shfl_up_sync(0xffffffffu, s4.x, off);
        float ny = __shfl_up_sync(0xffffffffu, s4.y, off);
        float nz = __shfl_up_sync(0xffffffffu, s4.z, off);
        float nw = __shfl_up_sync(0xffffffffu, s4.w, off);
        if (lane >= off) { s4.x += nx; s4.y += ny; s4.z += nz; s4.w += nw; }
    }
    if (lane == 31) swt[wid] = s4;
    __syncthreads();
    if (tid < 16) {
        float4 t4 = swt[tid];
        float4 c4 = t4;
        #pragma unroll
        for (int off = 1; off < 16; off <<= 1) {
            float nx = __shfl_up_sync(0x0000ffffu, c4.x, off);
            float ny = __shfl_up_sync(0x0000ffffu, c4.y, off);
            float nz = __shfl_up_sync(0x0000ffffu, c4.z, off);
            float nw = __shfl_up_sync(0x0000ffffu, c4.w, off);
            if (tid >= off) { c4.x += nx; c4.y += ny; c4.z += nz; c4.w += nw; }
        }
        swo[tid] = make_float4(c4.x - t4.x, c4.y - t4.y, c4.z - t4.z, c4.w - t4.w);
    }
    __syncthreads();
    float4 wo = swo[wid];
    float4 excl = make_float4(s4.x - pl.x + wo.x, s4.y - pl.y + wo.y,
                              s4.z - pl.z + wo.z, s4.w - pl.w + wo.w);
    ssum[tid] = excl;
    __syncthreads();
    float4 T = make_float4(swo[15].x + swt[15].x, swo[15].y + swt[15].y,
                           swo[15].z + swt[15].z, swo[15].w + swt[15].w);

    // per-i: first sorted position with v > thr
    float c = a0 * fi, thr = -c;
    int lo = 0, hi = 512;
    #pragma unroll
    for (int it = 0; it < 9; it++) {
        int mid = (lo + hi) >> 1;
        bool g = sk[mid] > thr;
        hi = g ? mid : hi;
        lo = g ? lo : mid + 1;
    }
    float4 E = (lo < 512) ? ssum[lo] : T;   // sums over positions < lo
    float A  = T.z - E.z;   // sum f e1, v>thr
    float Cs = T.x - E.x;   // sum e1,   v>thr
    float D  = E.y;         // sum e2,   v<=thr
    float Bs = E.w;         // sum f e2, v<=thr

    float s = c + vmax;
    float M = s > 0.f ? s : 0.2f * s;
    float alpha = __expf(s - M);
    float beta  = __expf(0.2f * s - M);
    float r = (alpha * A + beta * Bs) / (alpha * Cs + beta * D);
    d_xg[bt * NN + tid] = r > 0.f ? r : 0.f;
}

// ======================= enc input GEMM (+bias) ===========================
__global__ __launch_bounds__(256) void enc_gemm(const float* __restrict__ Wih,
                                                const float* __restrict__ bih,
                                                const float* __restrict__ bhh) {
    __shared__ float As[64][17];
    __shared__ float Bt[64][17];
    int tid = threadIdx.x;
    int tx = tid & 15, ty = tid >> 4;
    int mBase = blockIdx.y * 64, rBase = blockIdx.x * 64;
    float acc[4][4] = {};
    for (int k0 = 0; k0 < 512; k0 += 16) {
        #pragma unroll
        for (int i = tid; i < 1024; i += 256) {
            int rr = i >> 4, kk = i & 15;
            As[rr][kk] = d_xg[(mBase + rr) * 512 + k0 + kk];
            Bt[rr][kk] = Wih[(rBase + rr) * 512 + k0 + kk];
        }
        __syncthreads();
        #pragma unroll
        for (int kk = 0; kk < 16; kk++) {
            float a[4], bv[4];
            #pragma unroll
            for (int i = 0; i < 4; i++) a[i] = As[ty * 4 + i][kk];
            #pragma unroll
            for (int j = 0; j < 4; j++) bv[j] = Bt[tx * 4 + j][kk];
            #pragma unroll
            for (int i = 0; i < 4; i++)
                #pragma unroll
                for (int j = 0; j < 4; j++)
                    acc[i][j] = fmaf(a[i], bv[j], acc[i][j]);
        }
        __syncthreads();
    }
    #pragma unroll
    for (int i = 0; i < 4; i++) {
        int mm = mBase + ty * 4 + i;
        #pragma unroll
        for (int j = 0; j < 4; j++) {
            int r = rBase + tx * 4 + j;
            d_G[mm * 1024 + r] = acc[i][j] + bih[r] + bhh[r];
        }
    }
}

// ================= Weff GEMM: dec_Wih[1024,512] @ fc_W[512,256] ===========
__global__ __launch_bounds__(256) void wef_gemm(const float* __restrict__ decWih,
                                                const float* __restrict__ fcW) {
    __shared__ float As[64][17];
    __shared__ float Bt[16][68];
    int tid = threadIdx.x;
    int tx = tid & 15, ty = tid >> 4;
    int rBase = blockIdx.y * 64, kBase = blockIdx.x * 64;
    float acc[4][4] = {};
    for (int o0 = 0; o0 < 512; o0 += 16) {
        #pragma unroll
        for (int i = tid; i < 1024; i += 256) {
            int rr = i >> 4, oo = i & 15;
            As[rr][oo] = decWih[(rBase + rr) * 512 + o0 + oo];
        }
        #pragma unroll
        for (int i = tid; i < 1024; i += 256) {
            int oo = i >> 6, kk = i & 63;
            Bt[oo][kk] = fcW[(o0 + oo) * 256 + kBase + kk];
        }
        __syncthreads();
        #pragma unroll
        for (int oo = 0; oo < 16; oo++) {
            float a[4], bv[4];
            #pragma unroll
            for (int i = 0; i < 4; i++) a[i] = As[ty * 4 + i][oo];
            #pragma unroll
            for (int j = 0; j < 4; j++) bv[j] = Bt[oo][tx * 4 + j];
            #pragma unroll
            for (int i = 0; i < 4; i++)
                #pragma unroll
                for (int j = 0; j < 4; j++)
                    acc[i][j] = fmaf(a[i], bv[j], acc[i][j]);
        }
        __syncthreads();
    }
    #pragma unroll
    for (int i = 0; i < 4; i++)
        #pragma unroll
        for (int j = 0; j < 4; j++)
            d_Weff[(rBase + ty * 4 + i) * 256 + kBase + tx * 4 + j] = acc[i][j];
}

// ====================== persistent recurrent kernel =======================
__device__ __forceinline__ float sigf(float v) {
    return __fdividef(1.f, 1.f + __expf(-v));
}
__device__ __forceinline__ float tanh_pt(float v) {
    float t = __expf(-2.f * fabsf(v));             // no overflow
    float r = __fdividef(1.f - t, 1.f + t);
    return copysignf(r, v);
}
__device__ __forceinline__ float4 ldcg4(const float4* p) {
    float4 r;
    asm volatile("ld.global.cg.v4.f32 {%0,%1,%2,%3},[%4];"
                 : "=f"(r.x), "=f"(r.y), "=f"(r.z), "=f"(r.w) : "l"(p) : "memory");
    return r;
}
__device__ __forceinline__ int notsent(float4 r) {
    return (__float_as_uint(r.x) != 0xFFFFFFFFu) & (__float_as_uint(r.y) != 0xFFFFFFFFu) &
           (__float_as_uint(r.z) != 0xFFFFFFFFu) & (__float_as_uint(r.w) != 0xFFFFFFFFu);
}
// Poll step buffer until fully written, stage into padded smem [b*272 + k]
__device__ __forceinline__ void poll_load(const float* src, float4* sh4, int tid) {
    const float4* s4 = (const float4*)src;
    float4 r0, r1;
    for (;;) {
        r0 = ldcg4(s4 + tid);
        r1 = ldcg4(s4 + tid + 256);
        if (__syncthreads_and(notsent(r0) && notsent(r1))) break;
    }
    int i0 = tid, i1 = tid + 256;
    sh4[(i0 >> 6) * 68 + (i0 & 63)] = r0;
    sh4[(i1 >> 6) * 68 + (i1 & 63)] = r1;
    __syncthreads();
}

__global__ __launch_bounds__(256, 1) void rec_kernel(
        const float* __restrict__ encWhh, const float* __restrict__ decWih,
        const float* __restrict__ decWhh, const float* __restrict__ decBih,
        const float* __restrict__ decBhh, const float* __restrict__ fcW,
        const float* __restrict__ fcb, float* __restrict__ out) {
    __shared__ float sWe[8 * 256];
    __shared__ float sWdH[8 * 256];
    __shared__ float sWdc[8 * 256];
    __shared__ float sWf[4 * 256];
    __shared__ float4 sh4[8 * 68];          // h staged: [b*68 float4]
    __shared__ float sg[64];
    __shared__ float sc[16];
    __shared__ float sDb0[8];
    __shared__ float sDbE[8];
    __shared__ float sFb[4];

    int bk = blockIdx.x, tid = threadIdx.x;

    for (int i = tid; i < 8 * 256; i += 256) {
        int rl = i >> 8, k = i & 255;
        int grow = (rl >> 1) * 256 + bk * 2 + (rl & 1);
        sWe[i] = encWhh[grow * 256 + k];
        float wh = decWhh[grow * 256 + k];
        sWdH[i] = wh;
        sWdc[i] = d_Weff[grow * 256 + k] + wh;
    }
    for (int i = tid; i < 4 * 256; i += 256)
        sWf[i] = fcW[(bk * 4 + (i >> 8)) * 256 + (i & 255)];
    {
        int rl = tid >> 5, lane = tid & 31;
        int grow = (rl >> 1) * 256 + bk * 2 + (rl & 1);
        float p = 0.f;
        for (int o = lane; o < 512; o += 32)
            p = fmaf(decWih[grow * 512 + o], fcb[o], p);
        #pragma unroll
        for (int s = 16; s; s >>= 1) p += __shfl_xor_sync(0xffffffffu, p, s);
        if (lane == 0) {
            float db = decBih[grow] + decBhh[grow];
            sDb0[rl] = db;
            sDbE[rl] = db + p;
        }
    }
    if (tid < 4)  sFb[tid] = fcb[bk * 4 + tid];
    if (tid < 16) sc[tid] = 0.f;
    __syncthreads();

    const int o  = tid >> 2, kp = tid & 3;
    const int rl = o >> 3,   b  = o & 7;
    const int grow = (rl >> 1) * 256 + bk * 2 + (rl & 1);
    const int hidx = bk * 2;  // unit base

    // ---------------- encoder: 64 steps ----------------
    #pragma unroll 1
    for (int t = 0; t < 64; t++) {
        float gval = 0.f;
        if (kp == 0) gval = __ldg(&d_G[(b * 64 + t) * 1024 + grow]);
        float acc = 0.f;
        if (t > 0) {
            poll_load(d_hbuf + (t - 1) * 2048, sh4, tid);
            const float4* w4 = (const float4*)(sWe + rl * 256);
            const float4* h4 = sh4 + b * 68;
            #pragma unroll
            for (int i = 0; i < 16; i++) {
                float4 hv = h4[kp + 4 * i];
                float4 wv = w4[kp + 4 * i];
                acc = fmaf(hv.x, wv.x, acc); acc = fmaf(hv.y, wv.y, acc);
                acc = fmaf(hv.z, wv.z, acc); acc = fmaf(hv.w, wv.w, acc);
            }
        }
        acc += __shfl_xor_sync(0xffffffffu, acc, 1);
        acc += __shfl_xor_sync(0xffffffffu, acc, 2);
        if (kp == 0) sg[o] = acc + gval;
        __syncthreads();
        if (tid < 16) {
            int u = tid >> 3, bb = tid & 7;
            float gi = sg[(0 + u) * 8 + bb];
            float gf = sg[(2 + u) * 8 + bb];
            float gg = sg[(4 + u) * 8 + bb];
            float go = sg[(6 + u) * 8 + bb];
            float cc = sigf(gf) * sc[tid] + sigf(gi) * tanh_pt(gg);
            sc[tid] = cc;
            float hh = sigf(go) * tanh_pt(cc);
            __stcg(&d_hbuf[t * 2048 + bb * 256 + hidx + u], hh);
        }
    }

    // ---------------- decoder: 24 steps ----------------
    const int o2 = tid >> 3, kp8 = tid & 7;
    const int fr = o2 >> 3,  b2 = o2 & 7;

    #pragma unroll 1
    for (int dt = 0; dt < 24; dt++) {
        poll_load(d_hbuf + (63 + dt) * 2048, sh4, tid);

        if (dt >= 1) {  // pred for step dt-1 uses h at buffer 63+dt
            const float4* wf4 = (const float4*)(sWf + fr * 256);
            const float4* h4p = sh4 + b2 * 68;
            float pa = 0.f;
            #pragma unroll
            for (int i = 0; i < 8; i++) {
                float4 hv = h4p[kp8 + 8 * i];
                float4 wv = wf4[kp8 + 8 * i];
                pa = fmaf(hv.x, wv.x, pa); pa = fmaf(hv.y, wv.y, pa);
                pa = fmaf(hv.z, wv.z, pa); pa = fmaf(hv.w, wv.w, pa);
            }
            pa += __shfl_xor_sync(0xffffffffu, pa, 1);
            pa += __shfl_xor_sync(0xffffffffu, pa, 2);
            pa += __shfl_xor_sync(0xffffffffu, pa, 4);
            if (kp8 == 0)
                out[b2 * (NFLEN * NOUT) + (dt - 1) * NOUT + bk * 4 + fr] = pa + sFb[fr];
        }

        const float* wsel = (dt == 0) ? sWdH : sWdc;
        const float4* w4 = (const float4*)(wsel + rl * 256);
        const float4* h4 = sh4 + b * 68;
        float acc = 0.f;
        #pragma unroll
        for (int i = 0; i < 16; i++) {
            float4 hv = h4[kp + 4 * i];
            float4 wv = w4[kp + 4 * i];
            acc = fmaf(hv.x, wv.x, acc); acc = fmaf(hv.y, wv.y, acc);
            acc = fmaf(hv.z, wv.z, acc); acc = fmaf(hv.w, wv.w, acc);
        }
        acc += __shfl_xor_sync(0xffffffffu, acc, 1);
        acc += __shfl_xor_sync(0xffffffffu, acc, 2);
        if (kp == 0) sg[o] = acc + ((dt == 0) ? sDb0[rl] : sDbE[rl]);
        __syncthreads();
        if (tid < 16) {
            int u = tid >> 3, bb = tid & 7;
            float gi = sg[(0 + u) * 8 + bb];
            float gf = sg[(2 + u) * 8 + bb];
            float gg = sg[(4 + u) * 8 + bb];
            float go = sg[(6 + u) * 8 + bb];
            float cc = sigf(gf) * sc[tid] + sigf(gi) * tanh_pt(gg);
            sc[tid] = cc;
            float hh = sigf(go) * tanh_pt(cc);
            __stcg(&d_hbuf[(64 + dt) * 2048 + bb * 256 + hidx + u], hh);
        }
    }

    // final pred (dt=23) from buffer 87
    poll_load(d_hbuf + 87 * 2048, sh4, tid);
    {
        const float4* wf4 = (const float4*)(sWf + fr * 256);
        const float4* h4p = sh4 + b2 * 68;
        float pa = 0.f;
        #pragma unroll
        for (int i = 0; i < 8; i++) {
            float4 hv = h4p[kp8 + 8 * i];
            float4 wv = wf4[kp8 + 8 * i];
            pa = fmaf(hv.x, wv.x, pa); pa = fmaf(hv.y, wv.y, pa);
            pa = fmaf(hv.z, wv.z, pa); pa = fmaf(hv.w, wv.w, pa);
        }
        pa += __shfl_xor_sync(0xffffffffu, pa, 1);
        pa += __shfl_xor_sync(0xffffffffu, pa, 2);
        pa += __shfl_xor_sync(0xffffffffu, pa, 4);
        if (kp8 == 0)
            out[b2 * (NFLEN * NOUT) + 23 * NOUT + bk * 4 + fr] = pa + sFb[fr];
    }
}

// ============================== launcher ==================================
extern "C" void kernel_launch(void* const* d_in, const int* in_sizes, int n_in,
                              void* d_out, int out_size) {
    const float* x      = (const float*)d_in[0];
    const float* gatW   = (const float*)d_in[2];
    const float* gata   = (const float*)d_in[3];
    const float* encWih = (const float*)d_in[4];
    const float* encWhh = (const float*)d_in[5];
    const float* encbih = (const float*)d_in[6];
    const float* encbhh = (const float*)d_in[7];
    const float* decWih = (const float*)d_in[8];
    const float* decWhh = (const float*)d_in[9];
    const float* decbih = (const float*)d_in[10];
    const float* decbhh = (const float*)d_in[11];
    const float* fcW    = (const float*)d_in[12];
    const float* fcb    = (const float*)d_in[13];
    float* out = (float*)d_out;

    void* hb = nullptr;
    cudaGetSymbolAddress(&hb, d_hbuf);
    cudaMemsetAsync(hb, 0xFF, NSTEP * 2048 * sizeof(float), 0);

    wef_gemm<<<dim3(4, 16), 256>>>(decWih, fcW);
    gat_kernel<<<NB * NT, 512>>>(x, gatW, gata);
    enc_gemm<<<dim3(16, 8), 256>>>(encWih, encbih, encbhh);
    rec_kernel<<<NBLK, 256>>>(encWhh, decWih, decWhh, decbih, decbhh,
                              fcW, fcb, out);
}

// round 5
// speedup vs baseline: 1.6466x; 1.6466x over previous
#include <cuda_runtime.h>
#include <math.h>
#include <stdint.h>

#define NB 8
#define NT 64
#define NN 512
#define NH 256
#define NOUT 512
#define NFLEN 24

// ---------------- device scratch (no allocations allowed) ----------------
__device__ float d_xg[NB * NT * NN];          // GAT output  [B,T,N]
__device__ float d_G[NB * NT * 4 * NH];       // enc input preacts (+bias)
__device__ float d_Weffc[4 * NH * NH];        // dec_Wih @ fc_W + decWhh
__device__ float d_db0[4 * NH];               // dec bias (dt==0)
__device__ float d_dbE[4 * NH];               // dec bias + decWih@fcb

// ============================= GAT kernel =================================
__global__ __launch_bounds__(512) void gat_kernel(const float* __restrict__ x,
                                                  const float* __restrict__ gatW,
                                                  const float* __restrict__ gata) {
    __shared__ float  sk[512];
    __shared__ float  sf[512];
    __shared__ float4 ssum[512];
    __shared__ float  sred[16];
    __shared__ float4 swt[16];
    __shared__ float4 swo[16];

    int bt = blockIdx.x, tid = threadIdx.x;
    int lane = tid & 31, wid = tid >> 5;
    float W = gatW[0], a0 = gata[0], a1 = gata[1];
    float fi = x[bt * NN + tid] * W;
    float v = a1 * fi;

    float m = v;
    #pragma unroll
    for (int s = 16; s; s >>= 1) m = fmaxf(m, __shfl_xor_sync(0xffffffffu, m, s));
    if (lane == 0) sred[wid] = m;
    __syncthreads();
    if (tid < 32) {
        float t2 = (tid < 16) ? sred[tid] : -3.4e38f;
        #pragma unroll
        for (int s = 8; s; s >>= 1) t2 = fmaxf(t2, __shfl_xor_sync(0xffffffffu, t2, s));
        if (tid == 0) sred[0] = t2;
    }
    sk[tid] = v;
    sf[tid] = fi;
    __syncthreads();
    float vmax = sred[0];

    for (int k = 2; k <= 512; k <<= 1) {
        for (int j = k >> 1; j > 0; j >>= 1) {
            int ixj = tid ^ j;
            if (ixj > tid) {
                float ka = sk[tid], kb = sk[ixj];
                bool up = ((tid & k) == 0);
                if ((ka > kb) == up) {
                    sk[tid] = kb; sk[ixj] = ka;
                    float t = sf[tid]; sf[tid] = sf[ixj]; sf[ixj] = t;
                }
            }
            __syncthreads();
        }
    }

    float vs = sk[tid], fs = sf[tid];
    float p1 = __expf(vs - vmax);
    float p2 = __expf(0.2f * (vs - vmax));
    float4 pl = make_float4(p1, p2, fs * p1, fs * p2);

    float4 s4 = pl;
    #pragma unroll
    for (int off = 1; off < 32; off <<= 1) {
        float nx = __shfl_up_sync(0xffffffffu, s4.x, off);
        float ny = __shfl_up_sync(0xffffffffu, s4.y, off);
        float nz = __shfl_up_sync(0xffffffffu, s4.z, off);
        float nw = __shfl_up_sync(0xffffffffu, s4.w, off);
        if (lane >= off) { s4.x += nx; s4.y += ny; s4.z += nz; s4.w += nw; }
    }
    if (lane == 31) swt[wid] = s4;
    __syncthreads();
    if (tid < 16) {
        float4 t4 = swt[tid];
        float4 c4 = t4;
        #pragma unroll
        for (int off = 1; off < 16; off <<= 1) {
            float nx = __shfl_up_sync(0x0000ffffu, c4.x, off);
            float ny = __shfl_up_sync(0x0000ffffu, c4.y, off);
            float nz = __shfl_up_sync(0x0000ffffu, c4.z, off);
            float nw = __shfl_up_sync(0x0000ffffu, c4.w, off);
            if (tid >= off) { c4.x += nx; c4.y += ny; c4.z += nz; c4.w += nw; }
        }
        swo[tid] = make_float4(c4.x - t4.x, c4.y - t4.y, c4.z - t4.z, c4.w - t4.w);
    }
    __syncthreads();
    float4 wo = swo[wid];
    float4 excl = make_float4(s4.x - pl.x + wo.x, s4.y - pl.y + wo.y,
                              s4.z - pl.z + wo.z, s4.w - pl.w + wo.w);
    ssum[tid] = excl;
    __syncthreads();
    float4 T = make_float4(swo[15].x + swt[15].x, swo[15].y + swt[15].y,
                           swo[15].z + swt[15].z, swo[15].w + swt[15].w);

    float c = a0 * fi, thr = -c;
    int lo = 0, hi = 512;
    #pragma unroll
    for (int it = 0; it < 9; it++) {
        int mid = (lo + hi) >> 1;
        bool g = sk[mid] > thr;
        hi = g ? mid : hi;
        lo = g ? lo : mid + 1;
    }
    float4 E = (lo < 512) ? ssum[lo] : T;
    float A  = T.z - E.z;
    float Cs = T.x - E.x;
    float D  = E.y;
    float Bs = E.w;

    float s = c + vmax;
    float M = s > 0.f ? s : 0.2f * s;
    float alpha = __expf(s - M);
    float beta  = __expf(0.2f * s - M);
    float r = (alpha * A + beta * Bs) / (alpha * Cs + beta * D);
    d_xg[bt * NN + tid] = r > 0.f ? r : 0.f;
}

// ======================= enc input GEMM (+bias) ===========================
__global__ __launch_bounds__(256) void enc_gemm(const float* __restrict__ Wih,
                                                const float* __restrict__ bih,
                                                const float* __restrict__ bhh) {
    __shared__ float As[64][17];
    __shared__ float Bt[64][17];
    int tid = threadIdx.x;
    int tx = tid & 15, ty = tid >> 4;
    int mBase = blockIdx.y * 64, rBase = blockIdx.x * 64;
    float acc[4][4] = {};
    for (int k0 = 0; k0 < 512; k0 += 16) {
        #pragma unroll
        for (int i = tid; i < 1024; i += 256) {
            int rr = i >> 4, kk = i & 15;
            As[rr][kk] = d_xg[(mBase + rr) * 512 + k0 + kk];
            Bt[rr][kk] = Wih[(rBase + rr) * 512 + k0 + kk];
        }
        __syncthreads();
        #pragma unroll
        for (int kk = 0; kk < 16; kk++) {
            float a[4], bv[4];
            #pragma unroll
            for (int i = 0; i < 4; i++) a[i] = As[ty * 4 + i][kk];
            #pragma unroll
            for (int j = 0; j < 4; j++) bv[j] = Bt[tx * 4 + j][kk];
            #pragma unroll
            for (int i = 0; i < 4; i++)
                #pragma unroll
                for (int j = 0; j < 4; j++)
                    acc[i][j] = fmaf(a[i], bv[j], acc[i][j]);
        }
        __syncthreads();
    }
    #pragma unroll
    for (int i = 0; i < 4; i++) {
        int mm = mBase + ty * 4 + i;
        #pragma unroll
        for (int j = 0; j < 4; j++) {
            int r = rBase + tx * 4 + j;
            d_G[mm * 1024 + r] = acc[i][j] + bih[r] + bhh[r];
        }
    }
}

// ====== Weffc GEMM: dec_Wih[1024,512] @ fc_W[512,256] + decWhh ============
__global__ __launch_bounds__(256) void wef_gemm(const float* __restrict__ decWih,
                                                const float* __restrict__ fcW,
                                                const float* __restrict__ decWhh) {
    __shared__ float As[64][17];
    __shared__ float Bt[16][68];
    int tid = threadIdx.x;
    int tx = tid & 15, ty = tid >> 4;
    int rBase = blockIdx.y * 64, kBase = blockIdx.x * 64;
    float acc[4][4] = {};
    for (int o0 = 0; o0 < 512; o0 += 16) {
        #pragma unroll
        for (int i = tid; i < 1024; i += 256) {
            int rr = i >> 4, oo = i & 15;
            As[rr][oo] = decWih[(rBase + rr) * 512 + o0 + oo];
        }
        #pragma unroll
        for (int i = tid; i < 1024; i += 256) {
            int oo = i >> 6, kk = i & 63;
            Bt[oo][kk] = fcW[(o0 + oo) * 256 + kBase + kk];
        }
        __syncthreads();
        #pragma unroll
        for (int oo = 0; oo < 16; oo++) {
            float a[4], bv[4];
            #pragma unroll
            for (int i = 0; i < 4; i++) a[i] = As[ty * 4 + i][oo];
            #pragma unroll
            for (int j = 0; j < 4; j++) bv[j] = Bt[oo][tx * 4 + j];
            #pragma unroll
            for (int i = 0; i < 4; i++)
                #pragma unroll
                for (int j = 0; j < 4; j++)
                    acc[i][j] = fmaf(a[i], bv[j], acc[i][j]);
        }
        __syncthreads();
    }
    #pragma unroll
    for (int i = 0; i < 4; i++)
        #pragma unroll
        for (int j = 0; j < 4; j++) {
            int idx = (rBase + ty * 4 + i) * 256 + kBase + tx * 4 + j;
            d_Weffc[idx] = acc[i][j] + decWhh[idx];
        }
}

// ========== decoder bias precompute: db0, dbE = db0 + decWih@fcb ==========
__global__ __launch_bounds__(256) void dbias_kernel(const float* __restrict__ decWih,
                                                    const float* __restrict__ decBih,
                                                    const float* __restrict__ decBhh,
                                                    const float* __restrict__ fcb) {
    int row = blockIdx.x * 8 + (threadIdx.x >> 5);
    int lane = threadIdx.x & 31;
    float p = 0.f;
    for (int o = lane; o < 512; o += 32)
        p = fmaf(decWih[row * 512 + o], fcb[o], p);
    #pragma unroll
    for (int s = 16; s; s >>= 1) p += __shfl_xor_sync(0xffffffffu, p, s);
    if (lane == 0) {
        float db = decBih[row] + decBhh[row];
        d_db0[row] = db;
        d_dbE[row] = db + p;
    }
}

// ====================== clustered recurrent kernel ========================
__device__ __forceinline__ float sigf(float v) {
    return __fdividef(1.f, 1.f + __expf(-v));
}
__device__ __forceinline__ float tanh_pt(float v) {
    float t = __expf(-2.f * fabsf(v));
    float r = __fdividef(1.f - t, 1.f + t);
    return copysignf(r, v);
}
__device__ __forceinline__ uint32_t smem_u32(const void* p) {
    uint32_t a;
    asm("{ .reg .u64 t; cvta.to.shared.u64 t, %1; cvt.u32.u64 %0, t; }"
        : "=r"(a) : "l"(p));
    return a;
}
__device__ __forceinline__ void st_cluster(uint32_t laddr, uint32_t rank, float v) {
    uint32_t remote;
    asm volatile("mapa.shared::cluster.u32 %0, %1, %2;"
                 : "=r"(remote) : "r"(laddr), "r"(rank));
    asm volatile("st.shared::cluster.b32 [%0], %1;"
                 :: "r"(remote), "r"(__float_as_uint(v)) : "memory");
}
__device__ __forceinline__ void cluster_sync_hw() {
    asm volatile("barrier.cluster.arrive.aligned;" ::: "memory");
    asm volatile("barrier.cluster.wait.aligned;" ::: "memory");
}
__device__ __forceinline__ uint32_t ctarank() {
    uint32_t r;
    asm("mov.u32 %0, %%cluster_ctarank;" : "=r"(r));
    return r;
}

// h physical layout in smem: u -> (u>>6)*68 + (u&63)  (conflict-free)
__global__ __launch_bounds__(512, 1) __cluster_dims__(8, 1, 1)
void rec_kernel(const float* __restrict__ encWhh,
                const float* __restrict__ decWhh,
                const float* __restrict__ fcW,
                const float* __restrict__ fcb,
                float* __restrict__ out) {
    __shared__ float hland[4][272];
    __shared__ float sg[128];
    __shared__ float sdb0[128];
    __shared__ float sdbE[128];

    const int tid = threadIdx.x;
    const uint32_t rank = ctarank();
    const int b = blockIdx.x >> 3;

    const int r  = tid >> 2, kp = tid & 3;           // gate rows
    const int grow = ((r >> 5) << 8) + (int)rank * 32 + (r & 31);
    const int fr = tid >> 3, kq = tid & 7;           // pred rows
    const int frg = (int)rank * 64 + fr;

    // zero h buffers
    for (int i = tid; i < 4 * 272; i += 512) ((float*)hland)[i] = 0.f;
    if (tid < 128) {
        int g2 = ((tid >> 5) << 8) + (int)rank * 32 + (tid & 31);
        sdb0[tid] = d_db0[g2];
        sdbE[tid] = d_dbE[g2];
    }

    // encoder recurrent weights -> registers (16 float4 = 64 floats)
    float4 wv[16];
    {
        const float4* w4 = (const float4*)encWhh + grow * 64 + kp * 16;
        #pragma unroll
        for (int i = 0; i < 16; i++) wv[i] = __ldg(w4 + i);
    }
    float fbv = __ldg(&fcb[frg]);
    float c = 0.f;  // cell state, valid in tid<32
    const uint32_t hl_base = smem_u32(&hland[0][0]);

    __syncthreads();
    cluster_sync_hw();

    float gval = 0.f;
    if (kp == 0) gval = __ldg(&d_G[(b * 64 + 0) * 1024 + grow]);

    // ---------------- encoder: 64 steps ----------------
    #pragma unroll 1
    for (int t = 0; t < 64; t++) {
        const int cur = t & 3, nxt = (t + 1) & 3;
        const float4* h4 = (const float4*)&hland[cur][kp * 68];
        float acc = 0.f;
        #pragma unroll
        for (int i = 0; i < 16; i++) {
            float4 hv = h4[i];
            acc = fmaf(hv.x, wv[i].x, acc); acc = fmaf(hv.y, wv[i].y, acc);
            acc = fmaf(hv.z, wv[i].z, acc); acc = fmaf(hv.w, wv[i].w, acc);
        }
        acc += __shfl_xor_sync(0xffffffffu, acc, 1);
        acc += __shfl_xor_sync(0xffffffffu, acc, 2);
        if (kp == 0) {
            sg[r] = acc + gval;
            if (t < 63) gval = __ldg(&d_G[(b * 64 + t + 1) * 1024 + grow]);
        }
        __syncthreads();
        if (tid < 32) {
            int u = tid;
            float gi = sg[u], gf = sg[32 + u], gg = sg[64 + u], go = sg[96 + u];
            c = sigf(gf) * c + sigf(gi) * tanh_pt(gg);
            float hh = sigf(go) * tanh_pt(c);
            int gu = (int)rank * 32 + u;
            uint32_t la = hl_base + (uint32_t)(nxt * 272 + (gu >> 6) * 68 + (gu & 63)) * 4u;
            #pragma unroll
            for (uint32_t p = 0; p < 8; p++) st_cluster(la, p, hh);
        }
        cluster_sync_hw();
    }

    // phase switch: load decoder combined weights + fc weights into regs
    {
        const float4* w4 = (const float4*)d_Weffc + grow * 64 + kp * 16;
        #pragma unroll
        for (int i = 0; i < 16; i++) wv[i] = __ldg(w4 + i);
    }
    float4 fw[8];
    {
        const float4* f4 = (const float4*)fcW + frg * 64 + kq * 8;
        #pragma unroll
        for (int j = 0; j < 8; j++) fw[j] = __ldg(f4 + j);
    }

    // ---------------- decoder: 24 steps ----------------
    #pragma unroll 1
    for (int dt = 0; dt < 24; dt++) {
        const int s = 64 + dt;
        const int cur = s & 3, nxt = (s + 1) & 3;
        const float4* h4 = (const float4*)&hland[cur][kp * 68];
        float acc = 0.f;
        if (dt == 0) {
            const float4* dw4 = (const float4*)decWhh + grow * 64 + kp * 16;
            #pragma unroll
            for (int i = 0; i < 16; i++) {
                float4 hv = h4[i];
                float4 w = __ldg(dw4 + i);
                acc = fmaf(hv.x, w.x, acc); acc = fmaf(hv.y, w.y, acc);
                acc = fmaf(hv.z, w.z, acc); acc = fmaf(hv.w, w.w, acc);
            }
        } else {
            #pragma unroll
            for (int i = 0; i < 16; i++) {
                float4 hv = h4[i];
                acc = fmaf(hv.x, wv[i].x, acc); acc = fmaf(hv.y, wv[i].y, acc);
                acc = fmaf(hv.z, wv[i].z, acc); acc = fmaf(hv.w, wv[i].w, acc);
            }
        }
        acc += __shfl_xor_sync(0xffffffffu, acc, 1);
        acc += __shfl_xor_sync(0xffffffffu, acc, 2);
        if (kp == 0) sg[r] = acc;
        __syncthreads();
        if (tid < 32) {
            int u = tid;
            const float* bp = (dt == 0) ? sdb0 : sdbE;
            float gi = sg[u] + bp[u];
            float gf = sg[32 + u] + bp[32 + u];
            float gg = sg[64 + u] + bp[64 + u];
            float go = sg[96 + u] + bp[96 + u];
            c = sigf(gf) * c + sigf(gi) * tanh_pt(gg);
            float hh = sigf(go) * tanh_pt(c);
            int gu = (int)rank * 32 + u;
            uint32_t la = hl_base + (uint32_t)(nxt * 272 + (gu >> 6) * 68 + (gu & 63)) * 4u;
            #pragma unroll
            for (uint32_t p = 0; p < 8; p++) st_cluster(la, p, hh);
        }
        cluster_sync_hw();

        // pred(dt) from new h in hland[nxt]
        {
            const int kbase = (kq >> 1) * 68 + (kq & 1) * 32;
            const float4* hp4 = (const float4*)&hland[nxt][kbase];
            float pa = 0.f;
            #pragma unroll
            for (int j = 0; j < 8; j++) {
                float4 hv = hp4[j];
                pa = fmaf(hv.x, fw[j].x, pa); pa = fmaf(hv.y, fw[j].y, pa);
                pa = fmaf(hv.z, fw[j].z, pa); pa = fmaf(hv.w, fw[j].w, pa);
            }
            pa += __shfl_xor_sync(0xffffffffu, pa, 1);
            pa += __shfl_xor_sync(0xffffffffu, pa, 2);
            pa += __shfl_xor_sync(0xffffffffu, pa, 4);
            if (kq == 0)
                out[b * (NFLEN * NOUT) + dt * NOUT + frg] = pa + fbv;
        }
    }
}

// ============================== launcher ==================================
extern "C" void kernel_launch(void* const* d_in, const int* in_sizes, int n_in,
                              void* d_out, int out_size) {
    const float* x      = (const float*)d_in[0];
    const float* gatW   = (const float*)d_in[2];
    const float* gata   = (const float*)d_in[3];
    const float* encWih = (const float*)d_in[4];
    const float* encWhh = (const float*)d_in[5];
    const float* encbih = (const float*)d_in[6];
    const float* encbhh = (const float*)d_in[7];
    const float* decWih = (const float*)d_in[8];
    const float* decWhh = (const float*)d_in[9];
    const float* decbih = (const float*)d_in[10];
    const float* decbhh = (const float*)d_in[11];
    const float* fcW    = (const float*)d_in[12];
    const float* fcb    = (const float*)d_in[13];
    float* out = (float*)d_out;

    gat_kernel<<<NB * NT, 512>>>(x, gatW, gata);
    wef_gemm<<<dim3(4, 16), 256>>>(decWih, fcW, decWhh);
    dbias_kernel<<<128, 256>>>(decWih, decbih, decbhh, fcb);
    enc_gemm<<<dim3(16, 8), 256>>>(encWih, encbih, encbhh);
    rec_kernel<<<64, 512>>>(encWhh, decWhh, fcW, fcb, out);
}